// round 1
// baseline (speedup 1.0000x reference)
#include <cuda_runtime.h>
#include <cuda_bf16.h>

// GAT-style structured attention:
//   rh = inputs.reshape(M, L, F)
//   s_self[m]  = inputs[m,:] . a1            (a1 = a[0:L*F])
//   s_nbr[m,l] = rh[m,l,:] . a2              (a2 = a[L*F:L*F+F])
//   z = s_self + s_nbr ; e = leaky_relu(z, 0.2) ; masked (segment-sum==0) -> -1e30
//   att = softmax_l(e) ; h[m,f] = sum_l att[m,l]*rh[m,l,f]
//   out = h>0 ? h : expm1(h)
//
// Shapes (bench): M=50000, L=32, F=128. HBM-bound: one full pass over 819 MB.

#define L_SEG 32
#define F_DIM 128
#define TPB   256
#define WARPS (TPB / 32)          // 8
#define SPW   (L_SEG / WARPS)     // 4 segments per warp

__global__ __launch_bounds__(TPB, 8)
void gat_row_kernel(const float* __restrict__ x,
                    const float* __restrict__ a,
                    float* __restrict__ out,
                    int M)
{
    const int m    = blockIdx.x;
    if (m >= M) return;
    const int tid  = threadIdx.x;
    const int w    = tid >> 5;
    const int lane = tid & 31;

    __shared__ float s_nbr[L_SEG];
    __shared__ float s_msk[L_SEG];
    __shared__ float warp_self[WARPS];
    __shared__ float att[L_SEG];
    __shared__ float4 hp[WARPS * 32];

    const float4* __restrict__ xr = (const float4*)(x + (size_t)m * (L_SEG * F_DIM));
    const float4* __restrict__ a1 = (const float4*)a;                 // L*F floats
    const float4  a2 = __ldg(((const float4*)(a + L_SEG * F_DIM)) + lane);

    // ---- load the whole row into registers (coalesced, MLP=4 per thread) ----
    float4 v[SPW];
#pragma unroll
    for (int j = 0; j < SPW; ++j) {
        const int l = w * SPW + j;
        v[j] = xr[l * (F_DIM / 4) + lane];
    }

    // ---- per-segment dots + mask sums + self-score partials ----
    float self_part = 0.f;
#pragma unroll
    for (int j = 0; j < SPW; ++j) {
        const int l = w * SPW + j;
        const float4 vv = v[j];
        float ssum = vv.x + vv.y + vv.z + vv.w;
        float sn   = vv.x * a2.x + vv.y * a2.y + vv.z * a2.z + vv.w * a2.w;
        const float4 w1 = __ldg(a1 + l * (F_DIM / 4) + lane);
        self_part += vv.x * w1.x + vv.y * w1.y + vv.z * w1.z + vv.w * w1.w;
#pragma unroll
        for (int o = 16; o; o >>= 1) {
            ssum += __shfl_xor_sync(0xffffffffu, ssum, o);
            sn   += __shfl_xor_sync(0xffffffffu, sn,   o);
        }
        if (lane == 0) {
            s_nbr[l] = sn;
            s_msk[l] = (ssum != 0.0f) ? 1.0f : 0.0f;
        }
    }
#pragma unroll
    for (int o = 16; o; o >>= 1)
        self_part += __shfl_xor_sync(0xffffffffu, self_part, o);
    if (lane == 0) warp_self[w] = self_part;
    __syncthreads();

    // ---- softmax over 32 segments: warp 0, one lane per segment ----
    if (w == 0) {
        float s_self = 0.f;
#pragma unroll
        for (int i = 0; i < WARPS; ++i) s_self += warp_self[i];
        const float z = s_self + s_nbr[lane];
        float e = (z >= 0.0f) ? z : 0.2f * z;
        e = (s_msk[lane] != 0.0f) ? e : -1e30f;
        float mx = e;
#pragma unroll
        for (int o = 16; o; o >>= 1)
            mx = fmaxf(mx, __shfl_xor_sync(0xffffffffu, mx, o));
        const float ex = __expf(e - mx);
        float sum = ex;
#pragma unroll
        for (int o = 16; o; o >>= 1)
            sum += __shfl_xor_sync(0xffffffffu, sum, o);
        att[lane] = ex / sum;
    }
    __syncthreads();

    // ---- attention-weighted recombination from registers ----
    float4 h = make_float4(0.f, 0.f, 0.f, 0.f);
#pragma unroll
    for (int j = 0; j < SPW; ++j) {
        const float aL = att[w * SPW + j];
        h.x += aL * v[j].x;
        h.y += aL * v[j].y;
        h.z += aL * v[j].z;
        h.w += aL * v[j].w;
    }
    hp[w * 32 + lane] = h;
    __syncthreads();

    // ---- cross-warp reduce (8 partials per feature-quad) + epilogue ----
    if (tid < 32) {
        float4 acc = hp[tid];
#pragma unroll
        for (int i = 1; i < WARPS; ++i) {
            const float4 t = hp[i * 32 + tid];
            acc.x += t.x; acc.y += t.y; acc.z += t.z; acc.w += t.w;
        }
        acc.x = (acc.x > 0.f) ? acc.x : expm1f(acc.x);
        acc.y = (acc.y > 0.f) ? acc.y : expm1f(acc.y);
        acc.z = (acc.z > 0.f) ? acc.z : expm1f(acc.z);
        acc.w = (acc.w > 0.f) ? acc.w : expm1f(acc.w);
        ((float4*)(out + (size_t)m * F_DIM))[tid] = acc;
    }
}

extern "C" void kernel_launch(void* const* d_in, const int* in_sizes, int n_in,
                              void* d_out, int out_size)
{
    const float* x = (const float*)d_in[0];
    const float* a = (const float*)d_in[1];
    float* out = (float*)d_out;

    // Derive shapes from element counts (no device-scalar reads; capture-safe):
    //   in_sizes[0] = M*L*F, in_sizes[1] = F*(L+1), out_size = M*F
    const long long total = in_sizes[0];
    const int L = (int)(total / (long long)out_size);      // 32
    const int F = in_sizes[1] / (L + 1);                   // 128
    const int M = out_size / F;                            // 50000

    // Kernel is compiled for L=32, F=128 (the bench shape).
    gat_row_kernel<<<M, TPB>>>(x, a, out, M);
}

// round 2
// speedup vs baseline: 1.0595x; 1.0595x over previous
#include <cuda_runtime.h>
#include <cuda_bf16.h>

// GAT-style structured attention, shapes M=50000, L=32, F=128.
// R2: 8 rows per CTA; a1/a2 held in registers across rows (kills the 16KB/CTA
// a1 L1-hit traffic that capped L1tex at 84%); double-buffered row loads;
// redundant per-warp softmax (one fewer barrier, no att smem).

#define L_SEG 32
#define F_DIM 128
#define TPB   256
#define WARPS (TPB / 32)          // 8
#define SPW   (L_SEG / WARPS)     // 4 segments per warp
#define ROWS_PER_CTA 8

__global__ __launch_bounds__(TPB, 4)
void gat_row_kernel(const float* __restrict__ x,
                    const float* __restrict__ a,
                    float* __restrict__ out,
                    int M)
{
    const int tid  = threadIdx.x;
    const int w    = tid >> 5;
    const int lane = tid & 31;
    const int m0   = blockIdx.x * ROWS_PER_CTA;

    __shared__ float  s_nbr[L_SEG];
    __shared__ float  s_msk[L_SEG];
    __shared__ float  warp_self[WARPS];
    __shared__ float4 hp[WARPS * 32];

    // ---- per-thread weight slices, loaded ONCE, reused for all rows ----
    const float4* __restrict__ a1p = (const float4*)a;
    float4 a1r[SPW];
#pragma unroll
    for (int j = 0; j < SPW; ++j)
        a1r[j] = __ldg(a1p + (w * SPW + j) * (F_DIM / 4) + lane);
    const float4 a2 = __ldg(((const float4*)(a + L_SEG * F_DIM)) + lane);

    // ---- preload first row ----
    float4 v[SPW];
    {
        const float4* __restrict__ xr =
            (const float4*)(x + (size_t)m0 * (L_SEG * F_DIM));
#pragma unroll
        for (int j = 0; j < SPW; ++j)
            v[j] = xr[(w * SPW + j) * (F_DIM / 4) + lane];
    }

    for (int r = 0; r < ROWS_PER_CTA; ++r) {
        const int m = m0 + r;
        if (m >= M) break;

        // ---- prefetch next row while we process this one ----
        float4 vn[SPW];
        if (r + 1 < ROWS_PER_CTA && m + 1 < M) {
            const float4* __restrict__ xr =
                (const float4*)(x + (size_t)(m + 1) * (L_SEG * F_DIM));
#pragma unroll
            for (int j = 0; j < SPW; ++j)
                vn[j] = xr[(w * SPW + j) * (F_DIM / 4) + lane];
        }

        // ---- per-segment dots + mask sums + self-score partials ----
        float self_part = 0.f;
#pragma unroll
        for (int j = 0; j < SPW; ++j) {
            const float4 vv = v[j];
            float ssum = vv.x + vv.y + vv.z + vv.w;
            float sn   = vv.x * a2.x + vv.y * a2.y + vv.z * a2.z + vv.w * a2.w;
            self_part += vv.x * a1r[j].x + vv.y * a1r[j].y
                       + vv.z * a1r[j].z + vv.w * a1r[j].w;
#pragma unroll
            for (int o = 16; o; o >>= 1) {
                ssum += __shfl_xor_sync(0xffffffffu, ssum, o);
                sn   += __shfl_xor_sync(0xffffffffu, sn,   o);
            }
            if (lane == 0) {
                s_nbr[w * SPW + j] = sn;
                s_msk[w * SPW + j] = (ssum != 0.0f) ? 1.0f : 0.0f;
            }
        }
#pragma unroll
        for (int o = 16; o; o >>= 1)
            self_part += __shfl_xor_sync(0xffffffffu, self_part, o);
        if (lane == 0) warp_self[w] = self_part;
        __syncthreads();

        // ---- softmax over 32 segments: EVERY warp redundantly (no 2nd sync) ----
        float s_self = 0.f;
#pragma unroll
        for (int i = 0; i < WARPS; ++i) s_self += warp_self[i];
        const float z = s_self + s_nbr[lane];
        float e = (z >= 0.0f) ? z : 0.2f * z;
        e = (s_msk[lane] != 0.0f) ? e : -1e30f;
        float mx = e;
#pragma unroll
        for (int o = 16; o; o >>= 1)
            mx = fmaxf(mx, __shfl_xor_sync(0xffffffffu, mx, o));
        const float ex = __expf(e - mx);
        float sum = ex;
#pragma unroll
        for (int o = 16; o; o >>= 1)
            sum += __shfl_xor_sync(0xffffffffu, sum, o);
        const float att_lane = ex / sum;   // attention for segment == lane

        // ---- attention-weighted recombination from registers ----
        float4 h = make_float4(0.f, 0.f, 0.f, 0.f);
#pragma unroll
        for (int j = 0; j < SPW; ++j) {
            const float aL = __shfl_sync(0xffffffffu, att_lane, w * SPW + j);
            h.x += aL * v[j].x;
            h.y += aL * v[j].y;
            h.z += aL * v[j].z;
            h.w += aL * v[j].w;
        }
        hp[w * 32 + lane] = h;
        __syncthreads();

        // ---- cross-warp reduce (warp 0) + epilogue + store ----
        if (w == 0) {
            float4 acc = hp[lane];
#pragma unroll
            for (int i = 1; i < WARPS; ++i) {
                const float4 t = hp[i * 32 + lane];
                acc.x += t.x; acc.y += t.y; acc.z += t.z; acc.w += t.w;
            }
            acc.x = (acc.x > 0.f) ? acc.x : expm1f(acc.x);
            acc.y = (acc.y > 0.f) ? acc.y : expm1f(acc.y);
            acc.z = (acc.z > 0.f) ? acc.z : expm1f(acc.z);
            acc.w = (acc.w > 0.f) ? acc.w : expm1f(acc.w);
            ((float4*)(out + (size_t)m * F_DIM))[lane] = acc;
        }

        // rotate buffers
#pragma unroll
        for (int j = 0; j < SPW; ++j) v[j] = vn[j];
    }
}

extern "C" void kernel_launch(void* const* d_in, const int* in_sizes, int n_in,
                              void* d_out, int out_size)
{
    const float* x = (const float*)d_in[0];
    const float* a = (const float*)d_in[1];
    float* out = (float*)d_out;

    // Derive shapes from element counts (capture-safe):
    //   in_sizes[0] = M*L*F, in_sizes[1] = F*(L+1), out_size = M*F
    const long long total = in_sizes[0];
    const int L = (int)(total / (long long)out_size);      // 32
    const int F = in_sizes[1] / (L + 1);                   // 128
    const int M = out_size / F;                            // 50000
    (void)L; (void)F;

    const int grid = (M + ROWS_PER_CTA - 1) / ROWS_PER_CTA;
    gat_row_kernel<<<grid, TPB>>>(x, a, out, M);
}

// round 3
// speedup vs baseline: 1.0730x; 1.0128x over previous
#include <cuda_runtime.h>
#include <cuda_bf16.h>

// GAT-style structured attention, M=50000, L=32, F=128.
// R3: "rotate-early" prefetch — next row's LDGs are issued into the (dead) v
// registers right after the h-recombination, so load latency overlaps the
// hp-store/barrier/output phase with ZERO extra registers. launch_bounds
// (256,5) caps regs ~48 -> 5 CTAs/SM (62.5% occ, was 48%).

#define L_SEG 32
#define F_DIM 128
#define TPB   256
#define WARPS (TPB / 32)          // 8
#define SPW   (L_SEG / WARPS)     // 4 segments per warp
#define ROWS_PER_CTA 8

__global__ __launch_bounds__(TPB, 5)
void gat_row_kernel(const float* __restrict__ x,
                    const float* __restrict__ a,
                    float* __restrict__ out,
                    int M)
{
    const int tid  = threadIdx.x;
    const int w    = tid >> 5;
    const int lane = tid & 31;
    const int m0   = blockIdx.x * ROWS_PER_CTA;

    __shared__ float  s_nbr[L_SEG];
    __shared__ float  s_msk[L_SEG];
    __shared__ float  warp_self[WARPS];
    __shared__ float4 hp[WARPS * 32];

    // ---- per-thread weight slices, loaded ONCE, reused for all rows ----
    const float4* __restrict__ a1p = (const float4*)a;
    float4 a1r[SPW];
#pragma unroll
    for (int j = 0; j < SPW; ++j)
        a1r[j] = __ldg(a1p + (w * SPW + j) * (F_DIM / 4) + lane);
    const float4 a2 = __ldg(((const float4*)(a + L_SEG * F_DIM)) + lane);

    // per-warp fixed offset within a row (in float4 units)
    const int seg_off = w * SPW * (F_DIM / 4) + lane;

    // ---- preload first row ----
    float4 v[SPW];
    {
        const float4* __restrict__ xr =
            (const float4*)(x + (size_t)m0 * (L_SEG * F_DIM));
#pragma unroll
        for (int j = 0; j < SPW; ++j)
            v[j] = xr[seg_off + j * (F_DIM / 4)];
    }

#pragma unroll 1
    for (int r = 0; r < ROWS_PER_CTA; ++r) {
        const int m = m0 + r;
        if (m >= M) break;

        // ---- per-segment dots + mask sums + self-score partials ----
        float self_part = 0.f;
#pragma unroll
        for (int j = 0; j < SPW; ++j) {
            const float4 vv = v[j];
            float ssum = vv.x + vv.y + vv.z + vv.w;
            float sn   = vv.x * a2.x + vv.y * a2.y + vv.z * a2.z + vv.w * a2.w;
            self_part += vv.x * a1r[j].x + vv.y * a1r[j].y
                       + vv.z * a1r[j].z + vv.w * a1r[j].w;
#pragma unroll
            for (int o = 16; o; o >>= 1) {
                ssum += __shfl_xor_sync(0xffffffffu, ssum, o);
                sn   += __shfl_xor_sync(0xffffffffu, sn,   o);
            }
            if (lane == 0) {
                s_nbr[w * SPW + j] = sn;
                s_msk[w * SPW + j] = (ssum != 0.0f) ? 1.0f : 0.0f;
            }
        }
#pragma unroll
        for (int o = 16; o; o >>= 1)
            self_part += __shfl_xor_sync(0xffffffffu, self_part, o);
        if (lane == 0) warp_self[w] = self_part;
        __syncthreads();

        // ---- softmax over 32 segments: every warp redundantly ----
        float s_self = 0.f;
#pragma unroll
        for (int i = 0; i < WARPS; ++i) s_self += warp_self[i];
        const float z = s_self + s_nbr[lane];
        float e = (z >= 0.0f) ? z : 0.2f * z;
        e = (s_msk[lane] != 0.0f) ? e : -1e30f;
        float mx = e;
#pragma unroll
        for (int o = 16; o; o >>= 1)
            mx = fmaxf(mx, __shfl_xor_sync(0xffffffffu, mx, o));
        const float ex = __expf(e - mx);
        float sum = ex;
#pragma unroll
        for (int o = 16; o; o >>= 1)
            sum += __shfl_xor_sync(0xffffffffu, sum, o);
        const float att_lane = ex / sum;   // attention for segment == lane

        // ---- attention-weighted recombination from registers ----
        float4 h = make_float4(0.f, 0.f, 0.f, 0.f);
#pragma unroll
        for (int j = 0; j < SPW; ++j) {
            const float aL = __shfl_sync(0xffffffffu, att_lane, w * SPW + j);
            h.x += aL * v[j].x;
            h.y += aL * v[j].y;
            h.z += aL * v[j].z;
            h.w += aL * v[j].w;
        }

        // ---- v is now DEAD: issue next row's loads into it immediately ----
        // (overlaps DRAM latency with the hp/barrier/output phase below)
        {
            int mn = m + 1;
            if (mn >= M) mn = m;                 // clamp: harmless re-read
            const float4* __restrict__ xr =
                (const float4*)(x + (size_t)mn * (L_SEG * F_DIM));
#pragma unroll
            for (int j = 0; j < SPW; ++j)
                v[j] = xr[seg_off + j * (F_DIM / 4)];
        }

        hp[w * 32 + lane] = h;
        __syncthreads();

        // ---- cross-warp reduce (warp 0) + epilogue + store ----
        if (w == 0) {
            float4 acc = hp[lane];
#pragma unroll
            for (int i = 1; i < WARPS; ++i) {
                const float4 t = hp[i * 32 + lane];
                acc.x += t.x; acc.y += t.y; acc.z += t.z; acc.w += t.w;
            }
            acc.x = (acc.x > 0.f) ? acc.x : expm1f(acc.x);
            acc.y = (acc.y > 0.f) ? acc.y : expm1f(acc.y);
            acc.z = (acc.z > 0.f) ? acc.z : expm1f(acc.z);
            acc.w = (acc.w > 0.f) ? acc.w : expm1f(acc.w);
            ((float4*)(out + (size_t)m * F_DIM))[lane] = acc;
        }
    }
}

extern "C" void kernel_launch(void* const* d_in, const int* in_sizes, int n_in,
                              void* d_out, int out_size)
{
    const float* x = (const float*)d_in[0];
    const float* a = (const float*)d_in[1];
    float* out = (float*)d_out;

    // Derive shapes from element counts (capture-safe):
    //   in_sizes[0] = M*L*F, in_sizes[1] = F*(L+1), out_size = M*F
    const long long total = in_sizes[0];
    const int L = (int)(total / (long long)out_size);      // 32
    const int F = in_sizes[1] / (L + 1);                   // 128
    const int M = out_size / F;                            // 50000
    (void)L; (void)F;

    const int grid = (M + ROWS_PER_CTA - 1) / ROWS_PER_CTA;
    gat_row_kernel<<<grid, TPB>>>(x, a, out, M);
}